// round 1
// baseline (speedup 1.0000x reference)
#include <cuda_runtime.h>
#include <math.h>

#define Bq 256
#define Hq 128
#define Nq 2048
#define KK 256   // effective K after folding decoder into bias
#define BM 128
#define BN 128
#define BK 32

// per-batch bias: c[b][h] = sum_k W[h][256+k] * dec[b][k]
__device__ float g_bias[Bq * Hq];

// ---------------------------------------------------------------------------
// Kernel 0: bias  c[b,h] = W3 @ dec[b]
// grid: (256), block: (128) = 4 warps; each warp owns 32 h rows.
// ---------------------------------------------------------------------------
__global__ void bias_kernel(const float* __restrict__ dec,
                            const float* __restrict__ W) {
    __shared__ float dsh[Hq];
    const int b = blockIdx.x;
    const int t = threadIdx.x;
    const int lane = t & 31;
    const int w = t >> 5;

    dsh[t] = dec[b * Hq + t];
    __syncthreads();

    for (int h = w * 32; h < w * 32 + 32; h++) {
        float p = 0.f;
#pragma unroll
        for (int i = 0; i < 4; i++) {
            int k = lane + 32 * i;
            p = fmaf(W[h * 384 + 256 + k], dsh[k], p);  // coalesced along k
        }
#pragma unroll
        for (int off = 16; off; off >>= 1)
            p += __shfl_xor_sync(0xffffffffu, p, off);
        if (lane == 0) g_bias[b * Hq + h] = p;
    }
}

// ---------------------------------------------------------------------------
// Kernel 1: fused GEMM + tanh + v-dot  -> raw scores in d_out [B, N]
//   C[h,n] = sum_k W[h,k] * H[k,n],  H rows 0..127 = static, 128..255 = dynamic
//   score[n] = sum_h v[h] * tanh(C[h,n] + c[b,h])
// grid: (N/BN=16, B=256), block: 256 threads (16x16), 8x8 register tile
// with split 4+4 fragments for conflict-free LDS.128.
// ---------------------------------------------------------------------------
__global__ __launch_bounds__(256) void score_kernel(
    const float* __restrict__ st, const float* __restrict__ dy,
    const float* __restrict__ v, const float* __restrict__ W,
    float* __restrict__ out) {
    __shared__ float As[BK][BM];      // W tile, transposed: As[k][h]
    __shared__ float Bs[BK][BN];      // hidden tile: Bs[k][n]
    __shared__ float vs[Hq];
    __shared__ float cs[Hq];
    __shared__ float red[16][BN];

    const int b  = blockIdx.y;
    const int n0 = blockIdx.x * BN;
    const int t  = threadIdx.x;
    const int tx = t & 15;
    const int ty = t >> 4;

    if (t < Hq) {
        vs[t] = v[t];
        cs[t] = g_bias[b * Hq + t];
    }

    float acc[8][8];
#pragma unroll
    for (int i = 0; i < 8; i++)
#pragma unroll
        for (int j = 0; j < 8; j++) acc[i][j] = 0.f;

    const float* base_st = st + (size_t)b * Hq * Nq;
    const float* base_dy = dy + (size_t)b * Hq * Nq;

    for (int k0 = 0; k0 < KK; k0 += BK) {
        // --- load A tile: W[h][k0..k0+32), store transposed As[k][h] ---
#pragma unroll
        for (int i = 0; i < 4; i++) {
            int idx = t + 256 * i;            // 0..1023 float4 slots
            int h   = idx >> 3;               // 0..127
            int c4  = idx & 7;                // 0..7
            float4 wv = *(const float4*)&W[h * 384 + k0 + c4 * 4];
            As[c4 * 4 + 0][h] = wv.x;
            As[c4 * 4 + 1][h] = wv.y;
            As[c4 * 4 + 2][h] = wv.z;
            As[c4 * 4 + 3][h] = wv.w;
        }
        // --- load B tile: hidden[k0+row][n0 + ...], coalesced float4 ---
#pragma unroll
        for (int i = 0; i < 4; i++) {
            int idx = t + 256 * i;
            int row = idx >> 5;               // 0..31
            int c4  = idx & 31;               // 0..31
            int gk  = k0 + row;
            const float* src = (gk < Hq) ? (base_st + (size_t)gk * Nq)
                                         : (base_dy + (size_t)(gk - Hq) * Nq);
            *(float4*)&Bs[row][c4 * 4] = *(const float4*)&src[n0 + c4 * 4];
        }
        __syncthreads();

#pragma unroll
        for (int k = 0; k < BK; k++) {
            float4 a0 = *(const float4*)&As[k][ty * 4];
            float4 a1 = *(const float4*)&As[k][ty * 4 + 64];
            float4 b0 = *(const float4*)&Bs[k][tx * 4];
            float4 b1 = *(const float4*)&Bs[k][tx * 4 + 64];
            float af[8] = {a0.x, a0.y, a0.z, a0.w, a1.x, a1.y, a1.z, a1.w};
            float bf[8] = {b0.x, b0.y, b0.z, b0.w, b1.x, b1.y, b1.z, b1.w};
#pragma unroll
            for (int i = 0; i < 8; i++)
#pragma unroll
                for (int j = 0; j < 8; j++)
                    acc[i][j] = fmaf(af[i], bf[j], acc[i][j]);
        }
        __syncthreads();
    }

    // --- epilogue: tanh(acc + c[h]), dot with v[h], partial per n ---
    float part[8] = {0.f, 0.f, 0.f, 0.f, 0.f, 0.f, 0.f, 0.f};
#pragma unroll
    for (int i = 0; i < 8; i++) {
        int h = (i < 4) ? (ty * 4 + i) : (64 + ty * 4 + (i - 4));
        float vh = vs[h];
        float ch = cs[h];
#pragma unroll
        for (int j = 0; j < 8; j++) {
            float x  = acc[i][j] + ch;
            float th = tanhf(x);
            part[j] = fmaf(vh, th, part[j]);
        }
    }
    *(float4*)&red[ty][tx * 4]      = make_float4(part[0], part[1], part[2], part[3]);
    *(float4*)&red[ty][tx * 4 + 64] = make_float4(part[4], part[5], part[6], part[7]);
    __syncthreads();

    if (t < BN) {
        float s = 0.f;
#pragma unroll
        for (int r = 0; r < 16; r++) s += red[r][t];
        out[(size_t)b * Nq + n0 + t] = s;
    }
}

// ---------------------------------------------------------------------------
// Kernel 2: in-place row softmax over N=2048. grid (256), block (256).
// ---------------------------------------------------------------------------
__global__ __launch_bounds__(256) void softmax_kernel(float* __restrict__ out) {
    __shared__ float sm[256];
    const int b = blockIdx.x;
    const int t = threadIdx.x;
    float* row = out + (size_t)b * Nq;

    float vals[8];
    float m = -1e30f;
#pragma unroll
    for (int i = 0; i < 8; i++) {
        vals[i] = row[t + 256 * i];
        m = fmaxf(m, vals[i]);
    }
    sm[t] = m;
    __syncthreads();
    for (int s = 128; s > 0; s >>= 1) {
        if (t < s) sm[t] = fmaxf(sm[t], sm[t + s]);
        __syncthreads();
    }
    const float M = sm[0];
    __syncthreads();

    float sum = 0.f;
#pragma unroll
    for (int i = 0; i < 8; i++) {
        vals[i] = __expf(vals[i] - M);
        sum += vals[i];
    }
    sm[t] = sum;
    __syncthreads();
    for (int s = 128; s > 0; s >>= 1) {
        if (t < s) sm[t] += sm[t + s];
        __syncthreads();
    }
    const float inv = 1.f / sm[0];
#pragma unroll
    for (int i = 0; i < 8; i++) row[t + 256 * i] = vals[i] * inv;
}

// ---------------------------------------------------------------------------
extern "C" void kernel_launch(void* const* d_in, const int* in_sizes, int n_in,
                              void* d_out, int out_size) {
    const float* st  = (const float*)d_in[0];  // static_hidden  [B,H,N]
    const float* dy  = (const float*)d_in[1];  // dynamic_hidden [B,H,N]
    const float* dec = (const float*)d_in[2];  // decoder_hidden [B,H]
    const float* v   = (const float*)d_in[3];  // v [1,1,H]
    const float* W   = (const float*)d_in[4];  // W [1,H,3H]
    float* out = (float*)d_out;                // [B,1,N]

    bias_kernel<<<Bq, Hq>>>(dec, W);
    dim3 grid(Nq / BN, Bq);
    score_kernel<<<grid, 256>>>(st, dy, v, W, out);
    softmax_kernel<<<Bq, 256>>>(out);
}